// round 16
// baseline (speedup 1.0000x reference)
#include <cuda_runtime.h>
#include <cuda_fp16.h>
#include <math.h>
#include <stdint.h>

// ---------------- problem constants ----------------
#define NROWS  8192
#define DIMK   512
#define CCLS   1000
#define WPR    32
#define NPAD   1024
#define NBLK   64            // NROWS / 128
#define NCH16  8             // DIMK / 64 (fp16 k64 chunks)
#define NTILES 2080          // NBLK*(NBLK+1)/2

// ---------------- device scratch (static) ----------------
__device__ unsigned g_featA16[NROWS * DIMK / 2];
__device__ unsigned g_featB16[NROWS * DIMK / 2];
__device__ float    g_proxy[NPAD * DIMK];
__device__ float    g_inv[NROWS];
__device__ float    g_invp[NPAD];
__device__ unsigned g_bits[NROWS * WPR];
__device__ unsigned g_bitsA[NROWS * 256];
__device__ unsigned g_bitsB[NROWS * 256];
__device__ float    g_pos[NROWS];
__device__ int      g_top1[NROWS];
__device__ int      g_candcnt[NROWS];
__device__ int      g_notconf[NROWS];
__device__ int      g_perm[NROWS];
__device__ int      g_old2new[NROWS];
__device__ int      g_nc;
__device__ float    g_part[NBLK * NROWS];
__device__ float    g_redl[32];
__device__ int      g_redc[32];
__device__ int      g_redn[32];
__device__ int      g_lcnt;

// ---------------- small helpers ----------------
__device__ __forceinline__ uint32_t smem_u32(const void* p) {
    uint32_t a;
    asm("{ .reg .u64 t; cvta.to.shared.u64 t, %1; cvt.u32.u64 %0, t; }" : "=r"(a) : "l"(p));
    return a;
}
__device__ __forceinline__ float4 lds128(uint32_t a) {
    float4 r;
    asm volatile("ld.shared.v4.f32 {%0,%1,%2,%3}, [%4];"
                 : "=f"(r.x), "=f"(r.y), "=f"(r.z), "=f"(r.w) : "r"(a));
    return r;
}
__device__ __forceinline__ void cp16(uint32_t dst, const void* src) {
    asm volatile("cp.async.cg.shared.global [%0], [%1], 16;" :: "r"(dst), "l"(src));
}
__device__ __forceinline__ void cp_commit() { asm volatile("cp.async.commit_group;"); }
template <int N> __device__ __forceinline__ void cp_wait() {
    asm volatile("cp.async.wait_group %0;" :: "n"(N) : "memory");
}
__device__ __forceinline__ void mma_f16(float c[4], const uint32_t a[4], const uint32_t b[2]) {
    asm volatile(
        "mma.sync.aligned.m16n8k16.row.col.f32.f16.f16.f32 "
        "{%0,%1,%2,%3}, {%4,%5,%6,%7}, {%8,%9}, {%0,%1,%2,%3};"
        : "+f"(c[0]), "+f"(c[1]), "+f"(c[2]), "+f"(c[3])
        : "r"(a[0]), "r"(a[1]), "r"(a[2]), "r"(a[3]), "r"(b[0]), "r"(b[1]));
}
__device__ __forceinline__ void mma_s8(int c[4], const uint32_t a[4], const uint32_t b[2]) {
    asm volatile(
        "mma.sync.aligned.m16n8k32.row.col.s32.s8.s8.s32 "
        "{%0,%1,%2,%3}, {%4,%5,%6,%7}, {%8,%9}, {%0,%1,%2,%3};"
        : "+r"(c[0]), "+r"(c[1]), "+r"(c[2]), "+r"(c[3])
        : "r"(a[0]), "r"(a[1]), "r"(a[2]), "r"(a[3]), "r"(b[0]), "r"(b[1]));
}

// ---------------- GEMM core helpers (fused sim) ----------------
__device__ __forceinline__ void ldg_stage(uint32_t st, const char* a, const char* b, int tid)
{
#pragma unroll
    for (int ii = 0; ii < 4; ii++) {
        int o = (tid + (ii << 8)) << 4;
        cp16(st + o, a + o);
        cp16(st + 16384 + o, b + o);
    }
    cp_commit();
}

__device__ __forceinline__ void compute_chunk_h(uint32_t Ab, uint32_t Bb,
                                                float (&acc)[4][4][4], int wr, int wc, int lane)
{
#pragma unroll
    for (int s = 0; s < 4; s++) {
        uint32_t b[4][2];
#pragma unroll
        for (int pl = 0; pl < 2; pl++) {
            float4 bv = lds128(Bb + (((((s << 3) | (wc * 2 + pl)) << 5) | lane) << 4));
            b[2*pl][0]   = __float_as_uint(bv.x); b[2*pl][1]   = __float_as_uint(bv.y);
            b[2*pl+1][0] = __float_as_uint(bv.z); b[2*pl+1][1] = __float_as_uint(bv.w);
        }
#pragma unroll
        for (int mt = 0; mt < 4; mt++) {
            float4 av = lds128(Ab + (((((s << 3) | (wr * 4 + mt)) << 5) | lane) << 4));
            uint32_t a[4] = { __float_as_uint(av.x), __float_as_uint(av.y),
                              __float_as_uint(av.z), __float_as_uint(av.w) };
#pragma unroll
            for (int nt = 0; nt < 4; nt++)
                mma_f16(acc[mt][nt], a, b[nt]);
        }
    }
}

__device__ __forceinline__ void compute_chunk_i(uint32_t Ab, uint32_t Bb,
                                                int (&acc)[4][4][4], int wr, int wc, int lane)
{
#pragma unroll
    for (int s = 0; s < 4; s++) {
        uint32_t b[4][2];
#pragma unroll
        for (int pl = 0; pl < 2; pl++) {
            float4 bv = lds128(Bb + (((((s << 3) | (wc * 2 + pl)) << 5) | lane) << 4));
            b[2*pl][0]   = __float_as_uint(bv.x); b[2*pl][1]   = __float_as_uint(bv.y);
            b[2*pl+1][0] = __float_as_uint(bv.z); b[2*pl+1][1] = __float_as_uint(bv.w);
        }
#pragma unroll
        for (int mt = 0; mt < 4; mt++) {
            float4 av = lds128(Ab + (((((s << 3) | (wr * 4 + mt)) << 5) | lane) << 4));
            uint32_t a[4] = { __float_as_uint(av.x), __float_as_uint(av.y),
                              __float_as_uint(av.z), __float_as_uint(av.w) };
#pragma unroll
            for (int nt = 0; nt < 4; nt++)
                mma_s8(acc[mt][nt], a, b[nt]);
        }
    }
}

// ======= prep0: [0,128) sgemm64 | 128 perm | [129,1153) feat inv-norm ========
__global__ __launch_bounds__(256)
void prep0_kernel(const float* __restrict__ A, const float* __restrict__ B,
                  float* __restrict__ C, const int* __restrict__ conf,
                  const float* __restrict__ feat)
{
    int bx = blockIdx.x;
    int t = threadIdx.x;
    if (bx < 128) {
        // ---- sgemm64: C(1000,512) = A(1000,512) @ B(512,512)^T ----
        __shared__ float As[16][64];
        __shared__ float Bs[16][64];
        int tr = t >> 4, tc = t & 15;
        int row0 = (bx >> 3) * 64, col0 = (bx & 7) * 64;
        int ldrow = t >> 2, ldk = (t & 3) * 4;
        float acc[4][4];
#pragma unroll
        for (int x = 0; x < 4; x++)
#pragma unroll
            for (int y = 0; y < 4; y++) acc[x][y] = 0.0f;
        for (int k0 = 0; k0 < DIMK; k0 += 16) {
            __syncthreads();
            {
                float4 va = make_float4(0,0,0,0), vb = make_float4(0,0,0,0);
                if (row0 + ldrow < CCLS) va = *(const float4*)&A[(size_t)(row0 + ldrow) * DIMK + k0 + ldk];
                vb = *(const float4*)&B[(size_t)(col0 + ldrow) * DIMK + k0 + ldk];
                As[ldk+0][ldrow]=va.x; As[ldk+1][ldrow]=va.y; As[ldk+2][ldrow]=va.z; As[ldk+3][ldrow]=va.w;
                Bs[ldk+0][ldrow]=vb.x; Bs[ldk+1][ldrow]=vb.y; Bs[ldk+2][ldrow]=vb.z; Bs[ldk+3][ldrow]=vb.w;
            }
            __syncthreads();
#pragma unroll
            for (int kk = 0; kk < 16; kk++) {
                float a[4], b[4];
                *(float4*)&a[0] = *(const float4*)&As[kk][tr*4];
                *(float4*)&b[0] = *(const float4*)&Bs[kk][tc*4];
#pragma unroll
                for (int x = 0; x < 4; x++)
#pragma unroll
                    for (int y = 0; y < 4; y++) acc[x][y] = fmaf(a[x], b[y], acc[x][y]);
            }
        }
#pragma unroll
        for (int x = 0; x < 4; x++) {
            int r = row0 + tr*4 + x;
            if (r < CCLS)
#pragma unroll
                for (int y = 0; y < 4; y++)
                    C[(size_t)r * DIMK + col0 + tc*4 + y] = acc[x][y];
        }
    } else if (bx == 128) {
        // ---- perm: conf-first stable permutation ----
        __shared__ int wtot[8];
        int warp = t >> 5, lane = t & 31;
        int cnt = 0;
        for (int q = 0; q < 32; q++) cnt += (conf[t * 32 + q] != 0) ? 1 : 0;
        int sc = cnt;
#pragma unroll
        for (int o = 1; o < 32; o <<= 1) {
            int v = __shfl_up_sync(0xFFFFFFFFu, sc, o);
            if (lane >= o) sc += v;
        }
        if (lane == 31) wtot[warp] = sc;
        __syncthreads();
        int woff = 0, nc = 0;
#pragma unroll
        for (int w = 0; w < 8; w++) {
            if (w < warp) woff += wtot[w];
            nc += wtot[w];
        }
        int exc = woff + sc - cnt;
        int pc = exc, pn = nc + (t * 32 - exc);
        for (int q = 0; q < 32; q++) {
            int i = t * 32 + q;
            int pos = (conf[i] != 0) ? pc++ : pn++;
            g_old2new[i] = pos;
            g_perm[pos] = i;
        }
        if (t == 0) { g_nc = nc; g_lcnt = 0; }
    } else {
        // ---- feat inverse L2 norms: 8 rows per block ----
        int row = (bx - 129) * 8 + (t >> 5);
        int lane = t & 31;
        const float4* p = (const float4*)(feat + (size_t)row * DIMK);
        float ss = 0.0f;
#pragma unroll
        for (int q = 0; q < 4; q++) {
            float4 v = p[lane + 32 * q];
            ss += v.x*v.x + v.y*v.y + v.z*v.z + v.w*v.w;
        }
#pragma unroll
        for (int o = 16; o; o >>= 1) ss += __shfl_xor_sync(0xFFFFFFFFu, ss, o);
        if (lane == 0) g_inv[row] = 1.0f / fmaxf(sqrtf(ss), 1e-12f);
    }
}

// ---------------- proxy inverse L2 norms (small) ----------------
__global__ void inv_proxy_kernel()
{
    int row = blockIdx.x * 8 + (threadIdx.x >> 5);
    int lane = threadIdx.x & 31;
    if (row >= CCLS) return;
    const float4* p = (const float4*)(g_proxy + (size_t)row * DIMK);
    float ss = 0.0f;
#pragma unroll
    for (int q = 0; q < 4; q++) {
        float4 v = p[lane + 32 * q];
        ss += v.x*v.x + v.y*v.y + v.z*v.z + v.w*v.w;
    }
#pragma unroll
    for (int o = 16; o; o >>= 1) ss += __shfl_xor_sync(0xFFFFFFFFu, ss, o);
    if (lane == 0) g_invp[row] = 1.0f / fmaxf(sqrtf(ss), 1e-12f);
}

// ================= prep1: blocks 0..511 frag_feat, 512..8703 row_prob ========
#define PREP1_SMEM 33664
__global__ __launch_bounds__(256)
void prep1_kernel(const float* __restrict__ in, const float* __restrict__ prob,
                  const int* __restrict__ conf)
{
    extern __shared__ char psm[];
    int bx = blockIdx.x;
    int t = threadIdx.x;

    if (bx < 512) {
        // ---- frag_feat ----
        float (*tile)[65] = (float(*)[65])psm;
        int kc = bx & 7, blk = bx >> 3;
        int row = t >> 1, half = t & 1;
        int orig = g_perm[blk * 128 + row];
        float inv = g_inv[orig];
        const float* src = in + (size_t)orig * DIMK + kc * 64 + half * 32;
#pragma unroll
        for (int q = 0; q < 8; q++) {
            float4 v = *(const float4*)(src + q * 4);
            int c = half * 32 + q * 4;
            tile[row][c+0] = v.x * inv; tile[row][c+1] = v.y * inv;
            tile[row][c+2] = v.z * inv; tile[row][c+3] = v.w * inv;
        }
        __syncthreads();
        size_t base = ((size_t)blk * NCH16 + kc) * 4096;
#pragma unroll
        for (int it = 0; it < 16; it++) {
            int o = t + it * 256;
            int reg = o & 3, lane = (o >> 2) & 31, m = (o >> 7) & 7, s = o >> 10;
            int rr = ((reg & 1) << 3) | (lane >> 2);
            int kk = ((lane & 3) << 1) | ((reg >> 1) << 3);
            int r0 = (m << 4) | rr, k0 = (s << 4) | kk;
            __half2 h = __floats2half2_rn(tile[r0][k0], tile[r0][k0+1]);
            g_featA16[base + o] = *(unsigned*)&h;
        }
#pragma unroll
        for (int it = 0; it < 16; it++) {
            int o = t + it * 256;
            int slot = o & 3, lane = (o >> 2) & 31, pair = (o >> 7) & 7, s = o >> 10;
            int n = (pair << 1) | (slot >> 1), breg = slot & 1;
            int col = (n << 3) | (lane >> 2);
            int kk = ((lane & 3) << 1) | (breg << 3);
            int k0 = (s << 4) | kk;
            __half2 h = __floats2half2_rn(tile[col][k0], tile[col][k0+1]);
            g_featB16[base + o] = *(unsigned*)&h;
        }
        return;
    }

    // ---- row_prob: i = bx - 512 ----
    unsigned* wbits = (unsigned*)psm;                    // [32]
    int*      ccls  = (int*)(psm + 128);                 // [1000]
    float*    cw    = (float*)(psm + 4128);              // [1000]
    float*    swb   = (float*)(psm + 8128);              // [8]
    int*      swi   = (int*)(psm + 8160);                // [8]
    int*      swc   = (int*)(psm + 8192);                // [8]
    int*      wsum  = (int*)(psm + 8224);                // [8]
    float*    sdw   = (float*)(psm + 8256);              // [8]

    int i = bx - 512;
    int warp = t >> 5, lane = t & 31;
    bool conf_i = conf[i] != 0;
    int np = g_old2new[i];
    if (t < WPR) wbits[t] = 0u;
    __syncthreads();

    // phase 1+2 merged: thread t owns classes 4t..4t+3 (t < 250)
    float pv[4] = {0.f, 0.f, 0.f, 0.f};
    float best = -INFINITY; int bidx = 0x7FFFFFFF; int cnt = 0;
    if (t < 250) {
        float4 p4 = *(const float4*)&prob[(size_t)i * CCLS + t * 4];
        pv[0] = p4.x; pv[1] = p4.y; pv[2] = p4.z; pv[3] = p4.w;
#pragma unroll
        for (int q = 0; q < 4; q++) {
            int c = t * 4 + q;
            if (pv[q] > best) { best = pv[q]; bidx = c; }
            if (pv[q] > 0.001f) { atomicOr(&wbits[c >> 5], 1u << (c & 31)); cnt++; }
        }
    }
    int cloc = cnt;
#pragma unroll
    for (int o = 16; o; o >>= 1) {
        float ov = __shfl_xor_sync(0xFFFFFFFFu, best, o);
        int   oi = __shfl_xor_sync(0xFFFFFFFFu, bidx, o);
        if (ov > best || (ov == best && oi < bidx)) { best = ov; bidx = oi; }
        cnt += __shfl_xor_sync(0xFFFFFFFFu, cnt, o);
    }
    if (lane == 0) { swb[warp] = best; swi[warp] = bidx; swc[warp] = cnt; }
    __syncthreads();

    float fb = -INFINITY; int t1 = 0x7FFFFFFF; int totc = 0;
#pragma unroll
    for (int w = 0; w < 8; w++) {
        float v = swb[w]; int ix = swi[w];
        if (v > fb || (v == fb && ix < t1)) { fb = v; t1 = ix; }
        totc += swc[w];
    }

    // candidate compaction (ascending class), nonconf only
    int loc = conf_i ? 0 : cloc;
    int sc = loc;
#pragma unroll
    for (int o = 1; o < 32; o <<= 1) {
        int v = __shfl_up_sync(0xFFFFFFFFu, sc, o);
        if (lane >= o) sc += v;
    }
    if (lane == 31) wsum[warp] = sc;
    __syncthreads();
    int woff = 0, ncand = 0;
#pragma unroll
    for (int w = 0; w < 8; w++) {
        if (w < warp) woff += wsum[w];
        ncand += wsum[w];
    }
    if (!conf_i && t < 250) {
        int pos = woff + sc - loc;
#pragma unroll
        for (int q = 0; q < 4; q++) {
            if (pv[q] > 0.001f) {
                int c = t * 4 + q;
                ccls[pos] = c; cw[pos] = pv[q] * g_invp[c]; pos++;
            }
        }
    }
    __syncthreads();

    // v = Σ w_c * proxy[c]; pos = (feat · v) * inv_i
    int d0 = t * 2, d1 = d0 + 1;
    float a0 = 0.0f, a1 = 0.0f;
    if (conf_i) {
        float w = g_invp[t1];
        a0 = w * g_proxy[(size_t)t1 * DIMK + d0];
        a1 = w * g_proxy[(size_t)t1 * DIMK + d1];
    } else {
        for (int j = 0; j < ncand; j++) {
            int c = ccls[j]; float w = cw[j];
            a0 += w * g_proxy[(size_t)c * DIMK + d0];
            a1 += w * g_proxy[(size_t)c * DIMK + d1];
        }
    }
    float d = in[(size_t)i * DIMK + d0] * a0 + in[(size_t)i * DIMK + d1] * a1;
#pragma unroll
    for (int o = 16; o; o >>= 1) d += __shfl_xor_sync(0xFFFFFFFFu, d, o);
    if (lane == 0) sdw[warp] = d;
    __syncthreads();

    if (t == 0) {
        float s = 0.0f;
#pragma unroll
        for (int w = 0; w < 8; w++) s += sdw[w];
#pragma unroll
        for (int w = 0; w < WPR; w++) {
            unsigned word = conf_i ? (((t1 >> 5) == w) ? (1u << (t1 & 31)) : 0u) : wbits[w];
            g_bits[(size_t)np * WPR + w] = word;
        }
        g_top1[np] = t1;
        g_pos[np] = s * g_inv[i];
        g_candcnt[np] = conf_i ? 0 : totc;
        g_notconf[np] = conf_i ? 0 : 1;
    }
}

// ---------------- expand candidate bits -> s8 frag blobs (nonconf blocks) ----
__global__ __launch_bounds__(256)
void frag_bits_kernel()
{
    int chunk = blockIdx.x, blk = blockIdx.y;
    if (blk * 128 + 128 <= g_nc) return;
    int t = threadIdx.x;
    size_t base = ((size_t)blk * 8 + chunk) * 4096;
#pragma unroll
    for (int it = 0; it < 16; it++) {
        int o4 = t + it * 256;
        int reg  = o4 & 3;
        int lane = (o4 >> 2) & 31;
        int m    = (o4 >> 7) & 7;
        int s    = o4 >> 10;
        int rr  = ((reg & 1) << 3) | (lane >> 2);
        int row = blk * 128 + (m << 4) + rr;
        int c0  = chunk * 128 + s * 32 + (((reg >> 1) << 4) | ((lane & 3) << 2));
        unsigned w = g_bits[(size_t)row * WPR + (c0 >> 5)];
        unsigned nib = (w >> (c0 & 31)) & 0xFu;
        g_bitsA[base + o4] = (nib & 1u) | ((nib & 2u) << 7) | ((nib & 4u) << 14) | ((nib & 8u) << 21);
        int g   = (m << 1) | (reg >> 1);
        int col = blk * 128 + (g << 3) + (lane >> 2);
        int c0b = chunk * 128 + s * 32 + (((reg & 1) << 4) | ((lane & 3) << 2));
        unsigned wb = g_bits[(size_t)col * WPR + (c0b >> 5)];
        unsigned nb = (wb >> (c0b & 31)) & 0xFu;
        g_bitsB[base + o4] = (nb & 1u) | ((nb & 2u) << 7) | ((nb & 4u) << 14) | ((nb & 8u) << 21);
    }
}

// ---------------- fused sim (linearized upper-triangle grid) -----------------
#define GEMM_SMEM 98304
__device__ __forceinline__ void chunk_src(int k, int bi, int bj,
                                          const char*& a, const char*& b)
{
    if (k < 8) {
        a = (const char*)g_bitsA + (((size_t)bi * 8 + k) << 14);
        b = (const char*)g_bitsB + (((size_t)bj * 8 + k) << 14);
    } else {
        a = (const char*)g_featA16 + (((size_t)bi * 8 + (k - 8)) << 14);
        b = (const char*)g_featB16 + (((size_t)bj * 8 + (k - 8)) << 14);
    }
}

__global__ __launch_bounds__(256, 2)
void fused_sim_mma_kernel()
{
    int l = blockIdx.x;
    int r = (int)((sqrtf(8.0f * (float)l + 1.0f) - 1.0f) * 0.5f);
    while ((r + 1) * (r + 2) / 2 <= l) r++;
    while (r * (r + 1) / 2 > l) r--;
    int bi = 63 - r;
    int bj = bi + (l - r * (r + 1) / 2);

    extern __shared__ char smem[];
    uint32_t sb = smem_u32(smem);
    int tid = threadIdx.x, w = tid >> 5, lane = tid & 31;
    int wr = w >> 2, wc = w & 3;
    bool offdiag = (bj != bi);

    int nc = g_nc;
    bool modeBit = (bi * 128 + 128) <= nc;
    bool colConf = (bj * 128 + 128) <= nc;
    int nch = modeBit ? 8 : 16;
    int kofs = modeBit ? 8 : 0;

    union Acc { int i[4][4][4]; float f[4][4][4]; } acc;
#pragma unroll
    for (int mt = 0; mt < 4; mt++)
#pragma unroll
        for (int nt = 0; nt < 4; nt++)
#pragma unroll
            for (int r2 = 0; r2 < 4; r2++) acc.i[mt][nt][r2] = 0;

    uint32_t keep0 = 0, keep1 = 0;

    {
        const char *a, *b;
        chunk_src(kofs + 0, bi, bj, a, b); ldg_stage(sb,         a, b, tid);
        chunk_src(kofs + 1, bi, bj, a, b); ldg_stage(sb + 32768, a, b, tid);
    }
#pragma unroll 1
    for (int k = 0; k < nch; k++) {
        if (k < nch - 1) cp_wait<1>(); else cp_wait<0>();
        __syncthreads();
        if (k + 2 < nch) {
            const char *a, *b;
            chunk_src(kofs + k + 2, bi, bj, a, b);
            ldg_stage(sb + (uint32_t)((k + 2) % 3) * 32768u, a, b, tid);
        }
        uint32_t st = sb + (uint32_t)(k % 3) * 32768u;
        if (!modeBit && k < 8) compute_chunk_i(st, st + 16384, acc.i, wr, wc, lane);
        else                   compute_chunk_h(st, st + 16384, acc.f, wr, wc, lane);
        if (!modeBit && k == 7) {
#pragma unroll
            for (int mt = 0; mt < 4; mt++)
#pragma unroll
                for (int nt = 0; nt < 4; nt++)
#pragma unroll
                    for (int r2 = 0; r2 < 4; r2++) {
                        int idx = mt*16 + nt*4 + r2;
                        unsigned bit = (acc.i[mt][nt][r2] == 0) ? 1u : 0u;
                        if (idx < 32) keep0 |= bit << idx;
                        else          keep1 |= bit << (idx - 32);
                        acc.f[mt][nt][r2] = 0.0f;
                    }
        }
    }
    __syncthreads();

    unsigned* cbits = (unsigned*)smem;
    int*   ct1      = (int*)(smem + 16896);
    float* red      = (float*)(smem + 17408);
    float* colred   = (float*)(smem + 17408 + 2048);

    int t1r[4][2];
    if (modeBit) {
        if (colConf) {
            if (tid < 128) ct1[tid] = g_top1[bj * 128 + tid];
        } else {
            for (int idx = tid; idx < 128 * WPR; idx += 256)
                cbits[(idx >> 5) * 33 + (idx & 31)] = g_bits[(size_t)(bj * 128) * WPR + idx];
        }
#pragma unroll
        for (int mt = 0; mt < 4; mt++)
#pragma unroll
            for (int rh = 0; rh < 2; rh++)
                t1r[mt][rh] = g_top1[bi*128 + wr*64 + mt*16 + (lane >> 2) + rh*8];
    }
    __syncthreads();

    float rowacc[4][2], colacc[4][2];
#pragma unroll
    for (int mt = 0; mt < 4; mt++)
#pragma unroll
        for (int rh = 0; rh < 2; rh++) rowacc[mt][rh] = 0.0f;
#pragma unroll
    for (int nt = 0; nt < 4; nt++)
#pragma unroll
        for (int cb = 0; cb < 2; cb++) colacc[nt][cb] = 0.0f;

#pragma unroll
    for (int mt = 0; mt < 4; mt++)
#pragma unroll
        for (int nt = 0; nt < 4; nt++)
#pragma unroll
            for (int r2 = 0; r2 < 4; r2++) {
                int idx = mt*16 + nt*4 + r2;
                unsigned kp;
                if (modeBit) {
                    int t1 = t1r[mt][r2 >> 1];
                    int col_l = wc*32 + nt*8 + ((lane & 3) << 1) + (r2 & 1);
                    if (colConf) kp = (t1 != ct1[col_l]) ? 1u : 0u;
                    else kp = ((cbits[col_l*33 + (t1 >> 5)] >> (t1 & 31)) & 1u) ^ 1u;
                } else {
                    kp = ((idx < 32) ? (keep0 >> idx) : (keep1 >> (idx - 32))) & 1u;
                }
                float v = acc.f[mt][nt][r2];
                if (kp && v >= 1e-6f) {
                    float e = __expf(v);
                    rowacc[mt][r2 >> 1] += e;
                    colacc[nt][r2 & 1]  += e;
                }
            }

#pragma unroll
    for (int mt = 0; mt < 4; mt++)
#pragma unroll
        for (int rh = 0; rh < 2; rh++) {
            float v = rowacc[mt][rh];
            v += __shfl_xor_sync(0xFFFFFFFFu, v, 1);
            v += __shfl_xor_sync(0xFFFFFFFFu, v, 2);
            if ((lane & 3) == 0)
                red[(wr*64 + mt*16 + (lane >> 2) + rh*8) * 4 + wc] = v;
        }
#pragma unroll
    for (int nt = 0; nt < 4; nt++)
#pragma unroll
        for (int cb = 0; cb < 2; cb++) {
            float v = colacc[nt][cb];
            v += __shfl_xor_sync(0xFFFFFFFFu, v, 4);
            v += __shfl_xor_sync(0xFFFFFFFFu, v, 8);
            v += __shfl_xor_sync(0xFFFFFFFFu, v, 16);
            if ((lane >> 2) == 0)
                colred[(wc*32 + nt*8 + ((lane & 3) << 1) + cb) * 2 + wr] = v;
        }
    __syncthreads();
    if (tid < 128) {
        float s = red[tid*4] + red[tid*4+1] + red[tid*4+2] + red[tid*4+3];
        g_part[(size_t)bj * NROWS + bi*128 + tid] = s;
        if (offdiag)
            g_part[(size_t)bi * NROWS + bj*128 + tid] = colred[tid*2] + colred[tid*2+1];
    }
}

// ---------------- loss reduction (fused 2-stage via last-block flag) ---------
__global__ void loss_kernel(float* __restrict__ out)
{
    __shared__ float sl[256];
    __shared__ int   sc[256];
    __shared__ int   sn[256];
    __shared__ bool  amlast;
    int t = threadIdx.x;
    int i = blockIdx.x * 256 + t;
    float pos = g_pos[i];
    float S = expf(pos);
#pragma unroll 8
    for (int s = 0; s < NBLK; s++) S += g_part[(size_t)s * NROWS + i];
    sl[t] = logf(S) - pos;
    sc[t] = g_candcnt[i];
    sn[t] = g_notconf[i];
    __syncthreads();
    for (int s = 128; s; s >>= 1) {
        if (t < s) { sl[t] += sl[t+s]; sc[t] += sc[t+s]; sn[t] += sn[t+s]; }
        __syncthreads();
    }
    if (t == 0) {
        g_redl[blockIdx.x] = sl[0];
        g_redc[blockIdx.x] = sc[0];
        g_redn[blockIdx.x] = sn[0];
        __threadfence();
        int old = atomicAdd(&g_lcnt, 1);
        amlast = (old == 31);
    }
    __syncthreads();
    if (amlast && t < 32) {
        float l = g_redl[t];
        int   c = g_redc[t];
        int   n = g_redn[t];
#pragma unroll
        for (int o = 16; o; o >>= 1) {
            l += __shfl_xor_sync(0xFFFFFFFFu, l, o);
            c += __shfl_xor_sync(0xFFFFFFFFu, c, o);
            n += __shfl_xor_sync(0xFFFFFFFFu, n, o);
        }
        if (t == 0) {
            out[0] = l / (float)NROWS;
            out[1] = (n > 0) ? ((float)c / (float)n) : 0.0f;
        }
    }
}

// ---------------- launch ----------------
extern "C" void kernel_launch(void* const* d_in, const int* in_sizes, int n_in,
                              void* d_out, int out_size)
{
    const float* feature   = (const float*)d_in[0];
    const float* proxy_raw = (const float*)d_in[1];
    const float* cPw       = (const float*)d_in[2];
    const float* prob      = (const float*)d_in[3];
    const int*   conf      = (const int*)d_in[4];
    float* out = (float*)d_out;

    void* p_proxy;
    cudaGetSymbolAddress(&p_proxy, g_proxy);

    cudaFuncSetAttribute(prep1_kernel, cudaFuncAttributeMaxDynamicSharedMemorySize, PREP1_SMEM);
    cudaFuncSetAttribute(fused_sim_mma_kernel, cudaFuncAttributeMaxDynamicSharedMemorySize, GEMM_SMEM);

    // 0) sgemm (proxy projection) || perm || feat inv-norms
    prep0_kernel<<<129 + NROWS / 8, 256>>>(proxy_raw, cPw, (float*)p_proxy, conf, feature);
    // 1) proxy inverse norms (small)
    inv_proxy_kernel<<<(CCLS + 7) / 8, 256>>>();
    // 2) frag_feat (512 blocks) || row_prob (8192 blocks)
    prep1_kernel<<<512 + NROWS, 256, PREP1_SMEM>>>(feature, prob, conf);
    // 3) expand candidate bits (nonconf blocks only)
    frag_bits_kernel<<<dim3(8, NBLK), 256>>>();
    // 4) fused sim: linearized upper triangle, long (nonconf) tiles first
    fused_sim_mma_kernel<<<NTILES, 256, GEMM_SMEM>>>();
    // 5) loss + sc_num (2-stage fused, last block finalizes)
    loss_kernel<<<NROWS / 256, 256>>>(out);
}

// round 17
// speedup vs baseline: 1.0303x; 1.0303x over previous
#include <cuda_runtime.h>
#include <cuda_fp16.h>
#include <math.h>
#include <stdint.h>

// ---------------- problem constants ----------------
#define NROWS  8192
#define DIMK   512
#define CCLS   1000
#define WPR    32
#define NPAD   1024
#define NBLK   64            // NROWS / 128
#define NCH16  8             // DIMK / 64 (fp16 k64 chunks)
#define NTILES 2080          // NBLK*(NBLK+1)/2

// ---------------- device scratch (static) ----------------
__device__ unsigned g_featA16[NROWS * DIMK / 2];
__device__ unsigned g_featB16[NROWS * DIMK / 2];
__device__ float    g_proxy[NPAD * DIMK];
__device__ float    g_inv[NROWS];
__device__ float    g_invp[NPAD];
__device__ unsigned g_bits[NROWS * WPR];
__device__ unsigned g_bitsA[NROWS * 256];
__device__ unsigned g_bitsB[NROWS * 256];
__device__ float    g_pos[NROWS];
__device__ int      g_top1[NROWS];
__device__ int      g_candcnt[NROWS];
__device__ int      g_notconf[NROWS];
__device__ int      g_perm[NROWS];
__device__ int      g_old2new[NROWS];
__device__ int      g_nc;
__device__ float    g_part[NBLK * NROWS];
__device__ float    g_redl[32];
__device__ int      g_redc[32];
__device__ int      g_redn[32];
__device__ int      g_lcnt;

// ---------------- small helpers ----------------
__device__ __forceinline__ uint32_t smem_u32(const void* p) {
    uint32_t a;
    asm("{ .reg .u64 t; cvta.to.shared.u64 t, %1; cvt.u32.u64 %0, t; }" : "=r"(a) : "l"(p));
    return a;
}
__device__ __forceinline__ float4 lds128(uint32_t a) {
    float4 r;
    asm volatile("ld.shared.v4.f32 {%0,%1,%2,%3}, [%4];"
                 : "=f"(r.x), "=f"(r.y), "=f"(r.z), "=f"(r.w) : "r"(a));
    return r;
}
__device__ __forceinline__ void cp16(uint32_t dst, const void* src) {
    asm volatile("cp.async.cg.shared.global [%0], [%1], 16;" :: "r"(dst), "l"(src));
}
__device__ __forceinline__ void cp_commit() { asm volatile("cp.async.commit_group;"); }
template <int N> __device__ __forceinline__ void cp_wait() {
    asm volatile("cp.async.wait_group %0;" :: "n"(N) : "memory");
}
__device__ __forceinline__ void mma_f16(float c[4], const uint32_t a[4], const uint32_t b[2]) {
    asm volatile(
        "mma.sync.aligned.m16n8k16.row.col.f32.f16.f16.f32 "
        "{%0,%1,%2,%3}, {%4,%5,%6,%7}, {%8,%9}, {%0,%1,%2,%3};"
        : "+f"(c[0]), "+f"(c[1]), "+f"(c[2]), "+f"(c[3])
        : "r"(a[0]), "r"(a[1]), "r"(a[2]), "r"(a[3]), "r"(b[0]), "r"(b[1]));
}
__device__ __forceinline__ void mma_s8(int c[4], const uint32_t a[4], const uint32_t b[2]) {
    asm volatile(
        "mma.sync.aligned.m16n8k32.row.col.s32.s8.s8.s32 "
        "{%0,%1,%2,%3}, {%4,%5,%6,%7}, {%8,%9}, {%0,%1,%2,%3};"
        : "+r"(c[0]), "+r"(c[1]), "+r"(c[2]), "+r"(c[3])
        : "r"(a[0]), "r"(a[1]), "r"(a[2]), "r"(a[3]), "r"(b[0]), "r"(b[1]));
}

// ---------------- GEMM core helpers (fused sim) ----------------
__device__ __forceinline__ void ldg_stage(uint32_t st, const char* a, const char* b, int tid)
{
#pragma unroll
    for (int ii = 0; ii < 4; ii++) {
        int o = (tid + (ii << 8)) << 4;
        cp16(st + o, a + o);
        cp16(st + 16384 + o, b + o);
    }
    cp_commit();
}

__device__ __forceinline__ void compute_chunk_h(uint32_t Ab, uint32_t Bb,
                                                float (&acc)[4][4][4], int wr, int wc, int lane)
{
#pragma unroll
    for (int s = 0; s < 4; s++) {
        uint32_t b[4][2];
#pragma unroll
        for (int pl = 0; pl < 2; pl++) {
            float4 bv = lds128(Bb + (((((s << 3) | (wc * 2 + pl)) << 5) | lane) << 4));
            b[2*pl][0]   = __float_as_uint(bv.x); b[2*pl][1]   = __float_as_uint(bv.y);
            b[2*pl+1][0] = __float_as_uint(bv.z); b[2*pl+1][1] = __float_as_uint(bv.w);
        }
#pragma unroll
        for (int mt = 0; mt < 4; mt++) {
            float4 av = lds128(Ab + (((((s << 3) | (wr * 4 + mt)) << 5) | lane) << 4));
            uint32_t a[4] = { __float_as_uint(av.x), __float_as_uint(av.y),
                              __float_as_uint(av.z), __float_as_uint(av.w) };
#pragma unroll
            for (int nt = 0; nt < 4; nt++)
                mma_f16(acc[mt][nt], a, b[nt]);
        }
    }
}

__device__ __forceinline__ void compute_chunk_i(uint32_t Ab, uint32_t Bb,
                                                int (&acc)[4][4][4], int wr, int wc, int lane)
{
#pragma unroll
    for (int s = 0; s < 4; s++) {
        uint32_t b[4][2];
#pragma unroll
        for (int pl = 0; pl < 2; pl++) {
            float4 bv = lds128(Bb + (((((s << 3) | (wc * 2 + pl)) << 5) | lane) << 4));
            b[2*pl][0]   = __float_as_uint(bv.x); b[2*pl][1]   = __float_as_uint(bv.y);
            b[2*pl+1][0] = __float_as_uint(bv.z); b[2*pl+1][1] = __float_as_uint(bv.w);
        }
#pragma unroll
        for (int mt = 0; mt < 4; mt++) {
            float4 av = lds128(Ab + (((((s << 3) | (wr * 4 + mt)) << 5) | lane) << 4));
            uint32_t a[4] = { __float_as_uint(av.x), __float_as_uint(av.y),
                              __float_as_uint(av.z), __float_as_uint(av.w) };
#pragma unroll
            for (int nt = 0; nt < 4; nt++)
                mma_s8(acc[mt][nt], a, b[nt]);
        }
    }
}

// ================= prep0: blocks 0..127 sgemm64, block 128 perm ==============
__global__ __launch_bounds__(256)
void prep0_kernel(const float* __restrict__ A, const float* __restrict__ B,
                  float* __restrict__ C, const int* __restrict__ conf)
{
    int bx = blockIdx.x;
    int t = threadIdx.x;
    if (bx < 128) {
        __shared__ float As[16][64];
        __shared__ float Bs[16][64];
        int tr = t >> 4, tc = t & 15;
        int row0 = (bx >> 3) * 64, col0 = (bx & 7) * 64;
        int ldrow = t >> 2, ldk = (t & 3) * 4;
        float acc[4][4];
#pragma unroll
        for (int x = 0; x < 4; x++)
#pragma unroll
            for (int y = 0; y < 4; y++) acc[x][y] = 0.0f;
        for (int k0 = 0; k0 < DIMK; k0 += 16) {
            __syncthreads();
            {
                float4 va = make_float4(0,0,0,0), vb = make_float4(0,0,0,0);
                if (row0 + ldrow < CCLS) va = *(const float4*)&A[(size_t)(row0 + ldrow) * DIMK + k0 + ldk];
                vb = *(const float4*)&B[(size_t)(col0 + ldrow) * DIMK + k0 + ldk];
                As[ldk+0][ldrow]=va.x; As[ldk+1][ldrow]=va.y; As[ldk+2][ldrow]=va.z; As[ldk+3][ldrow]=va.w;
                Bs[ldk+0][ldrow]=vb.x; Bs[ldk+1][ldrow]=vb.y; Bs[ldk+2][ldrow]=vb.z; Bs[ldk+3][ldrow]=vb.w;
            }
            __syncthreads();
#pragma unroll
            for (int kk = 0; kk < 16; kk++) {
                float a[4], b[4];
                *(float4*)&a[0] = *(const float4*)&As[kk][tr*4];
                *(float4*)&b[0] = *(const float4*)&Bs[kk][tc*4];
#pragma unroll
                for (int x = 0; x < 4; x++)
#pragma unroll
                    for (int y = 0; y < 4; y++) acc[x][y] = fmaf(a[x], b[y], acc[x][y]);
            }
        }
#pragma unroll
        for (int x = 0; x < 4; x++) {
            int r = row0 + tr*4 + x;
            if (r < CCLS)
#pragma unroll
                for (int y = 0; y < 4; y++)
                    C[(size_t)r * DIMK + col0 + tc*4 + y] = acc[x][y];
        }
    } else {
        // ---- perm: conf-first stable permutation ----
        __shared__ int wtot[8];
        int warp = t >> 5, lane = t & 31;
        int cnt = 0;
        for (int q = 0; q < 32; q++) cnt += (conf[t * 32 + q] != 0) ? 1 : 0;
        int sc = cnt;
#pragma unroll
        for (int o = 1; o < 32; o <<= 1) {
            int v = __shfl_up_sync(0xFFFFFFFFu, sc, o);
            if (lane >= o) sc += v;
        }
        if (lane == 31) wtot[warp] = sc;
        __syncthreads();
        int woff = 0, nc = 0;
#pragma unroll
        for (int w = 0; w < 8; w++) {
            if (w < warp) woff += wtot[w];
            nc += wtot[w];
        }
        int exc = woff + sc - cnt;
        int pc = exc, pn = nc + (t * 32 - exc);
        for (int q = 0; q < 32; q++) {
            int i = t * 32 + q;
            int pos = (conf[i] != 0) ? pc++ : pn++;
            g_old2new[i] = pos;
            g_perm[pos] = i;
        }
        if (t == 0) { g_nc = nc; g_lcnt = 0; }
    }
}

// ---------------- merged inverse L2 norms (feat rows then proxy rows) --------
__global__ void inv_norm_all_kernel(const float* __restrict__ feat)
{
    int row = blockIdx.x * 8 + (threadIdx.x >> 5);
    int lane = threadIdx.x & 31;
    const float4* p;
    if (row < NROWS) {
        p = (const float4*)(feat + (size_t)row * DIMK);
    } else {
        int pr = row - NROWS;
        if (pr >= CCLS) return;
        p = (const float4*)(g_proxy + (size_t)pr * DIMK);
    }
    float ss = 0.0f;
#pragma unroll
    for (int q = 0; q < 4; q++) {
        float4 v = p[lane + 32 * q];
        ss += v.x*v.x + v.y*v.y + v.z*v.z + v.w*v.w;
    }
#pragma unroll
    for (int o = 16; o; o >>= 1) ss += __shfl_xor_sync(0xFFFFFFFFu, ss, o);
    if (lane == 0) {
        float inv = 1.0f / fmaxf(sqrtf(ss), 1e-12f);
        if (row < NROWS) g_inv[row] = inv; else g_invp[row - NROWS] = inv;
    }
}

// ================= prep1: blocks 0..511 frag_feat, 512..8703 row_prob ========
#define PREP1_SMEM 33664
__global__ __launch_bounds__(256)
void prep1_kernel(const float* __restrict__ in, const float* __restrict__ prob,
                  const int* __restrict__ conf)
{
    extern __shared__ char psm[];
    int bx = blockIdx.x;
    int t = threadIdx.x;

    if (bx < 512) {
        // ---- frag_feat ----
        float (*tile)[65] = (float(*)[65])psm;
        int kc = bx & 7, blk = bx >> 3;
        int row = t >> 1, half = t & 1;
        int orig = g_perm[blk * 128 + row];
        float inv = g_inv[orig];
        const float* src = in + (size_t)orig * DIMK + kc * 64 + half * 32;
#pragma unroll
        for (int q = 0; q < 8; q++) {
            float4 v = *(const float4*)(src + q * 4);
            int c = half * 32 + q * 4;
            tile[row][c+0] = v.x * inv; tile[row][c+1] = v.y * inv;
            tile[row][c+2] = v.z * inv; tile[row][c+3] = v.w * inv;
        }
        __syncthreads();
        size_t base = ((size_t)blk * NCH16 + kc) * 4096;
#pragma unroll
        for (int it = 0; it < 16; it++) {
            int o = t + it * 256;
            int reg = o & 3, lane = (o >> 2) & 31, m = (o >> 7) & 7, s = o >> 10;
            int rr = ((reg & 1) << 3) | (lane >> 2);
            int kk = ((lane & 3) << 1) | ((reg >> 1) << 3);
            int r0 = (m << 4) | rr, k0 = (s << 4) | kk;
            __half2 h = __floats2half2_rn(tile[r0][k0], tile[r0][k0+1]);
            g_featA16[base + o] = *(unsigned*)&h;
        }
#pragma unroll
        for (int it = 0; it < 16; it++) {
            int o = t + it * 256;
            int slot = o & 3, lane = (o >> 2) & 31, pair = (o >> 7) & 7, s = o >> 10;
            int n = (pair << 1) | (slot >> 1), breg = slot & 1;
            int col = (n << 3) | (lane >> 2);
            int kk = ((lane & 3) << 1) | (breg << 3);
            int k0 = (s << 4) | kk;
            __half2 h = __floats2half2_rn(tile[col][k0], tile[col][k0+1]);
            g_featB16[base + o] = *(unsigned*)&h;
        }
        return;
    }

    // ---- row_prob: i = bx - 512, float4 loads, merged phases ----
    unsigned* wbits = (unsigned*)psm;                    // [32]
    int*      ccls  = (int*)(psm + 128);                 // [1000]
    float*    cw    = (float*)(psm + 4128);              // [1000]
    float*    swb   = (float*)(psm + 8128);              // [8]
    int*      swi   = (int*)(psm + 8160);                // [8]
    int*      swc   = (int*)(psm + 8192);                // [8]
    int*      wsum  = (int*)(psm + 8224);                // [8]
    float*    sdw   = (float*)(psm + 8256);              // [8]

    int i = bx - 512;
    int warp = t >> 5, lane = t & 31;
    bool conf_i = conf[i] != 0;
    int np = g_old2new[i];
    if (t < WPR) wbits[t] = 0u;
    __syncthreads();

    float pv[4] = {0.f, 0.f, 0.f, 0.f};
    float best = -INFINITY; int bidx = 0x7FFFFFFF; int cnt = 0;
    if (t < 250) {
        float4 p4 = *(const float4*)&prob[(size_t)i * CCLS + t * 4];
        pv[0] = p4.x; pv[1] = p4.y; pv[2] = p4.z; pv[3] = p4.w;
#pragma unroll
        for (int q = 0; q < 4; q++) {
            int c = t * 4 + q;
            if (pv[q] > best) { best = pv[q]; bidx = c; }
            if (pv[q] > 0.001f) { atomicOr(&wbits[c >> 5], 1u << (c & 31)); cnt++; }
        }
    }
    int cloc = cnt;
#pragma unroll
    for (int o = 16; o; o >>= 1) {
        float ov = __shfl_xor_sync(0xFFFFFFFFu, best, o);
        int   oi = __shfl_xor_sync(0xFFFFFFFFu, bidx, o);
        if (ov > best || (ov == best && oi < bidx)) { best = ov; bidx = oi; }
        cnt += __shfl_xor_sync(0xFFFFFFFFu, cnt, o);
    }
    if (lane == 0) { swb[warp] = best; swi[warp] = bidx; swc[warp] = cnt; }
    __syncthreads();

    float fb = -INFINITY; int t1 = 0x7FFFFFFF; int totc = 0;
#pragma unroll
    for (int w = 0; w < 8; w++) {
        float v = swb[w]; int ix = swi[w];
        if (v > fb || (v == fb && ix < t1)) { fb = v; t1 = ix; }
        totc += swc[w];
    }

    int loc = conf_i ? 0 : cloc;
    int sc = loc;
#pragma unroll
    for (int o = 1; o < 32; o <<= 1) {
        int v = __shfl_up_sync(0xFFFFFFFFu, sc, o);
        if (lane >= o) sc += v;
    }
    if (lane == 31) wsum[warp] = sc;
    __syncthreads();
    int woff = 0, ncand = 0;
#pragma unroll
    for (int w = 0; w < 8; w++) {
        if (w < warp) woff += wsum[w];
        ncand += wsum[w];
    }
    if (!conf_i && t < 250) {
        int pos = woff + sc - loc;
#pragma unroll
        for (int q = 0; q < 4; q++) {
            if (pv[q] > 0.001f) {
                int c = t * 4 + q;
                ccls[pos] = c; cw[pos] = pv[q] * g_invp[c]; pos++;
            }
        }
    }
    __syncthreads();

    int d0 = t * 2, d1 = d0 + 1;
    float a0 = 0.0f, a1 = 0.0f;
    if (conf_i) {
        float w = g_invp[t1];
        a0 = w * g_proxy[(size_t)t1 * DIMK + d0];
        a1 = w * g_proxy[(size_t)t1 * DIMK + d1];
    } else {
        for (int j = 0; j < ncand; j++) {
            int c = ccls[j]; float w = cw[j];
            a0 += w * g_proxy[(size_t)c * DIMK + d0];
            a1 += w * g_proxy[(size_t)c * DIMK + d1];
        }
    }
    float d = in[(size_t)i * DIMK + d0] * a0 + in[(size_t)i * DIMK + d1] * a1;
#pragma unroll
    for (int o = 16; o; o >>= 1) d += __shfl_xor_sync(0xFFFFFFFFu, d, o);
    if (lane == 0) sdw[warp] = d;
    __syncthreads();

    if (t == 0) {
        float s = 0.0f;
#pragma unroll
        for (int w = 0; w < 8; w++) s += sdw[w];
#pragma unroll
        for (int w = 0; w < WPR; w++) {
            unsigned word = conf_i ? (((t1 >> 5) == w) ? (1u << (t1 & 31)) : 0u) : wbits[w];
            g_bits[(size_t)np * WPR + w] = word;
        }
        g_top1[np] = t1;
        g_pos[np] = s * g_inv[i];
        g_candcnt[np] = conf_i ? 0 : totc;
        g_notconf[np] = conf_i ? 0 : 1;
    }
}

// ---------------- expand candidate bits -> s8 frag blobs (nonconf blocks) ----
__global__ __launch_bounds__(256)
void frag_bits_kernel()
{
    int chunk = blockIdx.x, blk = blockIdx.y;
    if (blk * 128 + 128 <= g_nc) return;
    int t = threadIdx.x;
    size_t base = ((size_t)blk * 8 + chunk) * 4096;
#pragma unroll
    for (int it = 0; it < 16; it++) {
        int o4 = t + it * 256;
        int reg  = o4 & 3;
        int lane = (o4 >> 2) & 31;
        int m    = (o4 >> 7) & 7;
        int s    = o4 >> 10;
        int rr  = ((reg & 1) << 3) | (lane >> 2);
        int row = blk * 128 + (m << 4) + rr;
        int c0  = chunk * 128 + s * 32 + (((reg >> 1) << 4) | ((lane & 3) << 2));
        unsigned w = g_bits[(size_t)row * WPR + (c0 >> 5)];
        unsigned nib = (w >> (c0 & 31)) & 0xFu;
        g_bitsA[base + o4] = (nib & 1u) | ((nib & 2u) << 7) | ((nib & 4u) << 14) | ((nib & 8u) << 21);
        int g   = (m << 1) | (reg >> 1);
        int col = blk * 128 + (g << 3) + (lane >> 2);
        int c0b = chunk * 128 + s * 32 + (((reg & 1) << 4) | ((lane & 3) << 2));
        unsigned wb = g_bits[(size_t)col * WPR + (c0b >> 5)];
        unsigned nb = (wb >> (c0b & 31)) & 0xFu;
        g_bitsB[base + o4] = (nb & 1u) | ((nb & 2u) << 7) | ((nb & 4u) << 14) | ((nb & 8u) << 21);
    }
}

// ---------------- fused sim (linearized upper-triangle grid) -----------------
#define GEMM_SMEM 98304
__device__ __forceinline__ void chunk_src(int k, int bi, int bj,
                                          const char*& a, const char*& b)
{
    if (k < 8) {
        a = (const char*)g_bitsA + (((size_t)bi * 8 + k) << 14);
        b = (const char*)g_bitsB + (((size_t)bj * 8 + k) << 14);
    } else {
        a = (const char*)g_featA16 + (((size_t)bi * 8 + (k - 8)) << 14);
        b = (const char*)g_featB16 + (((size_t)bj * 8 + (k - 8)) << 14);
    }
}

__global__ __launch_bounds__(256, 2)
void fused_sim_mma_kernel()
{
    int l = blockIdx.x;
    int r = (int)((sqrtf(8.0f * (float)l + 1.0f) - 1.0f) * 0.5f);
    while ((r + 1) * (r + 2) / 2 <= l) r++;
    while (r * (r + 1) / 2 > l) r--;
    int bi = 63 - r;
    int bj = bi + (l - r * (r + 1) / 2);

    extern __shared__ char smem[];
    uint32_t sb = smem_u32(smem);
    int tid = threadIdx.x, w = tid >> 5, lane = tid & 31;
    int wr = w >> 2, wc = w & 3;
    bool offdiag = (bj != bi);

    int nc = g_nc;
    bool modeBit = (bi * 128 + 128) <= nc;
    bool colConf = (bj * 128 + 128) <= nc;
    int nch = modeBit ? 8 : 16;
    int kofs = modeBit ? 8 : 0;

    union Acc { int i[4][4][4]; float f[4][4][4]; } acc;
#pragma unroll
    for (int mt = 0; mt < 4; mt++)
#pragma unroll
        for (int nt = 0; nt < 4; nt++)
#pragma unroll
            for (int r2 = 0; r2 < 4; r2++) acc.i[mt][nt][r2] = 0;

    uint32_t keep0 = 0, keep1 = 0;

    {
        const char *a, *b;
        chunk_src(kofs + 0, bi, bj, a, b); ldg_stage(sb,         a, b, tid);
        chunk_src(kofs + 1, bi, bj, a, b); ldg_stage(sb + 32768, a, b, tid);
    }
#pragma unroll 1
    for (int k = 0; k < nch; k++) {
        if (k < nch - 1) cp_wait<1>(); else cp_wait<0>();
        __syncthreads();
        if (k + 2 < nch) {
            const char *a, *b;
            chunk_src(kofs + k + 2, bi, bj, a, b);
            ldg_stage(sb + (uint32_t)((k + 2) % 3) * 32768u, a, b, tid);
        }
        uint32_t st = sb + (uint32_t)(k % 3) * 32768u;
        if (!modeBit && k < 8) compute_chunk_i(st, st + 16384, acc.i, wr, wc, lane);
        else                   compute_chunk_h(st, st + 16384, acc.f, wr, wc, lane);
        if (!modeBit && k == 7) {
#pragma unroll
            for (int mt = 0; mt < 4; mt++)
#pragma unroll
                for (int nt = 0; nt < 4; nt++)
#pragma unroll
                    for (int r2 = 0; r2 < 4; r2++) {
                        int idx = mt*16 + nt*4 + r2;
                        unsigned bit = (acc.i[mt][nt][r2] == 0) ? 1u : 0u;
                        if (idx < 32) keep0 |= bit << idx;
                        else          keep1 |= bit << (idx - 32);
                        acc.f[mt][nt][r2] = 0.0f;
                    }
        }
    }
    __syncthreads();

    unsigned* cbits = (unsigned*)smem;
    int*   ct1      = (int*)(smem + 16896);
    float* red      = (float*)(smem + 17408);
    float* colred   = (float*)(smem + 17408 + 2048);

    int t1r[4][2];
    if (modeBit) {
        if (colConf) {
            if (tid < 128) ct1[tid] = g_top1[bj * 128 + tid];
        } else {
            for (int idx = tid; idx < 128 * WPR; idx += 256)
                cbits[(idx >> 5) * 33 + (idx & 31)] = g_bits[(size_t)(bj * 128) * WPR + idx];
        }
#pragma unroll
        for (int mt = 0; mt < 4; mt++)
#pragma unroll
            for (int rh = 0; rh < 2; rh++)
                t1r[mt][rh] = g_top1[bi*128 + wr*64 + mt*16 + (lane >> 2) + rh*8];
    }
    __syncthreads();

    float rowacc[4][2], colacc[4][2];
#pragma unroll
    for (int mt = 0; mt < 4; mt++)
#pragma unroll
        for (int rh = 0; rh < 2; rh++) rowacc[mt][rh] = 0.0f;
#pragma unroll
    for (int nt = 0; nt < 4; nt++)
#pragma unroll
        for (int cb = 0; cb < 2; cb++) colacc[nt][cb] = 0.0f;

#pragma unroll
    for (int mt = 0; mt < 4; mt++)
#pragma unroll
        for (int nt = 0; nt < 4; nt++)
#pragma unroll
            for (int r2 = 0; r2 < 4; r2++) {
                int idx = mt*16 + nt*4 + r2;
                unsigned kp;
                if (modeBit) {
                    int t1 = t1r[mt][r2 >> 1];
                    int col_l = wc*32 + nt*8 + ((lane & 3) << 1) + (r2 & 1);
                    if (colConf) kp = (t1 != ct1[col_l]) ? 1u : 0u;
                    else kp = ((cbits[col_l*33 + (t1 >> 5)] >> (t1 & 31)) & 1u) ^ 1u;
                } else {
                    kp = ((idx < 32) ? (keep0 >> idx) : (keep1 >> (idx - 32))) & 1u;
                }
                float v = acc.f[mt][nt][r2];
                if (kp && v >= 1e-6f) {
                    float e = __expf(v);
                    rowacc[mt][r2 >> 1] += e;
                    colacc[nt][r2 & 1]  += e;
                }
            }

#pragma unroll
    for (int mt = 0; mt < 4; mt++)
#pragma unroll
        for (int rh = 0; rh < 2; rh++) {
            float v = rowacc[mt][rh];
            v += __shfl_xor_sync(0xFFFFFFFFu, v, 1);
            v += __shfl_xor_sync(0xFFFFFFFFu, v, 2);
            if ((lane & 3) == 0)
                red[(wr*64 + mt*16 + (lane >> 2) + rh*8) * 4 + wc] = v;
        }
#pragma unroll
    for (int nt = 0; nt < 4; nt++)
#pragma unroll
        for (int cb = 0; cb < 2; cb++) {
            float v = colacc[nt][cb];
            v += __shfl_xor_sync(0xFFFFFFFFu, v, 4);
            v += __shfl_xor_sync(0xFFFFFFFFu, v, 8);
            v += __shfl_xor_sync(0xFFFFFFFFu, v, 16);
            if ((lane >> 2) == 0)
                colred[(wc*32 + nt*8 + ((lane & 3) << 1) + cb) * 2 + wr] = v;
        }
    __syncthreads();
    if (tid < 128) {
        float s = red[tid*4] + red[tid*4+1] + red[tid*4+2] + red[tid*4+3];
        g_part[(size_t)bj * NROWS + bi*128 + tid] = s;
        if (offdiag)
            g_part[(size_t)bi * NROWS + bj*128 + tid] = colred[tid*2] + colred[tid*2+1];
    }
}

// ---------------- loss reduction (fused 2-stage via last-block flag) ---------
__global__ void loss_kernel(float* __restrict__ out)
{
    __shared__ float sl[256];
    __shared__ int   sc[256];
    __shared__ int   sn[256];
    __shared__ bool  amlast;
    int t = threadIdx.x;
    int i = blockIdx.x * 256 + t;
    float pos = g_pos[i];
    float S = expf(pos);
#pragma unroll 8
    for (int s = 0; s < NBLK; s++) S += g_part[(size_t)s * NROWS + i];
    sl[t] = logf(S) - pos;
    sc[t] = g_candcnt[i];
    sn[t] = g_notconf[i];
    __syncthreads();
    for (int s = 128; s; s >>= 1) {
        if (t < s) { sl[t] += sl[t+s]; sc[t] += sc[t+s]; sn[t] += sn[t+s]; }
        __syncthreads();
    }
    if (t == 0) {
        g_redl[blockIdx.x] = sl[0];
        g_redc[blockIdx.x] = sc[0];
        g_redn[blockIdx.x] = sn[0];
        __threadfence();
        int old = atomicAdd(&g_lcnt, 1);
        amlast = (old == 31);
    }
    __syncthreads();
    if (amlast && t < 32) {
        float l = g_redl[t];
        int   c = g_redc[t];
        int   n = g_redn[t];
#pragma unroll
        for (int o = 16; o; o >>= 1) {
            l += __shfl_xor_sync(0xFFFFFFFFu, l, o);
            c += __shfl_xor_sync(0xFFFFFFFFu, c, o);
            n += __shfl_xor_sync(0xFFFFFFFFu, n, o);
        }
        if (t == 0) {
            out[0] = l / (float)NROWS;
            out[1] = (n > 0) ? ((float)c / (float)n) : 0.0f;
        }
    }
}

// ---------------- launch ----------------
extern "C" void kernel_launch(void* const* d_in, const int* in_sizes, int n_in,
                              void* d_out, int out_size)
{
    const float* feature   = (const float*)d_in[0];
    const float* proxy_raw = (const float*)d_in[1];
    const float* cPw       = (const float*)d_in[2];
    const float* prob      = (const float*)d_in[3];
    const int*   conf      = (const int*)d_in[4];
    float* out = (float*)d_out;

    void* p_proxy;
    cudaGetSymbolAddress(&p_proxy, g_proxy);

    cudaFuncSetAttribute(prep1_kernel, cudaFuncAttributeMaxDynamicSharedMemorySize, PREP1_SMEM);
    cudaFuncSetAttribute(fused_sim_mma_kernel, cudaFuncAttributeMaxDynamicSharedMemorySize, GEMM_SMEM);

    // 0) sgemm (proxy projection) || perm + loss-counter reset
    prep0_kernel<<<129, 256>>>(proxy_raw, cPw, (float*)p_proxy, conf);
    // 1) merged inverse norms (feat + proxy)
    inv_norm_all_kernel<<<(NROWS + CCLS + 7) / 8, 256>>>(feature);
    // 2) frag_feat (512 blocks) || row_prob (8192 blocks, float4 loads)
    prep1_kernel<<<512 + NROWS, 256, PREP1_SMEM>>>(feature, prob, conf);
    // 3) expand candidate bits (nonconf blocks only)
    frag_bits_kernel<<<dim3(8, NBLK), 256>>>();
    // 4) fused sim: linearized upper triangle, long (nonconf) tiles first
    fused_sim_mma_kernel<<<NTILES, 256, GEMM_SMEM>>>();
    // 5) loss + sc_num (2-stage fused, last block finalizes)
    loss_kernel<<<NROWS / 256, 256>>>(out);
}